// round 1
// baseline (speedup 1.0000x reference)
#include <cuda_runtime.h>

// Problem shape (fixed for this registry entry)
#define B   8
#define T   200
#define U1  101        // U+1
#define V   1024
#define US  102        // padded u-stride: odd (1-US) => conflict-free diagonal smem reads
#define NEGV (-1e30f)

// Compact gathered scores: [B][T][US]  (646KB each; device scratch, no allocs)
__device__ __align__(16) float g_blank[B * T * US];
__device__ __align__(16) float g_lc[B * T * US];

// ---------------------------------------------------------------------------
// Kernel 1: gather blank + label-emission scores out of the huge logits tensor
//   blank[b,t,u] = logits[b,t,u,0]
//   lc[b,t,u]    = (u==0) ? NEG : logits[b,t,u-1,labels[b,u-1]]
// Also zero-initializes the scalar output (d_out is poisoned by the harness).
// ---------------------------------------------------------------------------
__global__ void gather_kernel(const float* __restrict__ logits,
                              const int* __restrict__ labels,
                              float* __restrict__ out) {
    int idx = blockIdx.x * blockDim.x + threadIdx.x;
    if (idx == 0) out[0] = 0.0f;
    const int total = B * T * US;
    if (idx >= total) return;

    int u = idx % US;
    int t = (idx / US) % T;
    int b = idx / (US * T);

    float bv = NEGV, lv = NEGV;
    if (u < U1) {
        long base = ((long)(b * T + t) * U1 + u) * V;
        bv = logits[base];                     // blank channel
        if (u > 0) {
            int lab = labels[b * (U1 - 1) + (u - 1)];
            long base2 = ((long)(b * T + t) * U1 + (u - 1)) * V;
            lv = logits[base2 + lab];          // label-emission channel
        }
    }
    g_blank[idx] = bv;
    g_lc[idx]    = lv;
}

// ---------------------------------------------------------------------------
// Kernel 2: per-batch anti-diagonal wavefront DP.
//   alpha[t,u] = logaddexp( (t==0 ? base0 : alpha[t-1,u]+blank[t-1,u]),
//                           alpha[t,u-1] + lc[t,u] )
// One CTA per batch. Columns live on threads (u = tid); alpha[t-1,u] is a
// register, alpha[t,u-1] goes through a double-buffered smem row, one
// __syncthreads per diagonal. blank/lc staged into dynamic smem first.
// ---------------------------------------------------------------------------
__global__ void dp_kernel(const int* __restrict__ loglen,
                          const int* __restrict__ lablen,
                          float* __restrict__ out) {
    extern __shared__ float smem[];
    float* sm_blank = smem;              // T*US floats
    float* sm_lc    = smem + T * US;     // T*US floats
    __shared__ float sh_alpha[2][U1];

    const int b   = blockIdx.x;
    const int tid = threadIdx.x;

    // Stage this batch's compact arrays into shared memory (float4, coalesced)
    {
        const float4* src_b = reinterpret_cast<const float4*>(g_blank + b * T * US);
        const float4* src_l = reinterpret_cast<const float4*>(g_lc    + b * T * US);
        float4* dst_b = reinterpret_cast<float4*>(sm_blank);
        float4* dst_l = reinterpret_cast<float4*>(sm_lc);
        const int n4 = (T * US) / 4;     // 5100
        for (int i = tid; i < n4; i += blockDim.x) {
            dst_b[i] = src_b[i];
            dst_l[i] = src_l[i];
        }
    }
    __syncthreads();

    const int Tb = loglen[b];
    const int Lb = lablen[b];
    const int u  = tid;

    float a_reg = NEGV;  // alpha[t-1, u] for this column (valid once t>=1)

    #pragma unroll 1
    for (int d = 0; d < T + U1 - 1; ++d) {   // 300 diagonals
        float*       cur  = sh_alpha[d & 1];
        const float* prev = sh_alpha[(d & 1) ^ 1];
        int t = d - u;
        if (u < U1 && t >= 0 && t < T) {
            float left = (u == 0) ? NEGV : prev[u - 1];
            float base = (t == 0) ? ((u == 0) ? 0.0f : NEGV)
                                  : (a_reg + sm_blank[(t - 1) * US + u]);
            float y  = left + sm_lc[t * US + u];
            float m  = fmaxf(base, y);
            float dd = fminf(base, y) - m;
            a_reg = m + __logf(1.0f + __expf(dd));
            cur[u] = a_reg;
            if (t == Tb - 1 && u == Lb)
                atomicAdd(out, -a_reg * (1.0f / B));   // mean over batch
        }
        __syncthreads();
    }
}

// ---------------------------------------------------------------------------
extern "C" void kernel_launch(void* const* d_in, const int* in_sizes, int n_in,
                              void* d_out, int out_size) {
    const float* logits = (const float*)d_in[0];
    const int*   labels = (const int*)d_in[1];
    const int*   loglen = (const int*)d_in[2];
    const int*   lablen = (const int*)d_in[3];
    float* out = (float*)d_out;

    const int total = B * T * US;
    const int smem_bytes = 2 * T * US * (int)sizeof(float);  // 163200 bytes

    cudaFuncSetAttribute(dp_kernel,
                         cudaFuncAttributeMaxDynamicSharedMemorySize,
                         smem_bytes);

    gather_kernel<<<(total + 255) / 256, 256>>>(logits, labels, out);
    dp_kernel<<<B, 256, smem_bytes>>>(loglen, lablen, out);
}